// round 4
// baseline (speedup 1.0000x reference)
#include <cuda_runtime.h>

#define KCLS 256
#define WARPS_PER_BLOCK 8
#define THREADS (WARPS_PER_BLOCK * 32)

__device__ __forceinline__ float ex2f(float a) {
    float r; asm("ex2.approx.f32 %0, %1;" : "=f"(r) : "f"(a)); return r;
}
__device__ __forceinline__ float rcpf(float a) {
    float r; asm("rcp.approx.f32 %0, %1;" : "=f"(r) : "f"(a)); return r;
}

__global__ __launch_bounds__(THREADS)
void dbf_kernel(const int* __restrict__ data,
                const float* __restrict__ t,
                const float4* __restrict__ noise,
                float4* __restrict__ out,
                int nrows)
{
    __shared__ __align__(16) float sg[KCLS];
    __shared__ __align__(16) float sh[KCLS];

    const int tid  = threadIdx.x;
    const int lane = tid & 31;
    const int warp = tid >> 5;

    // Closed-form Cholesky of C0 = (K+0.001) I - 11^T:
    //   T_k = a/(k-a), g_k = sqrt(a+T_k), h_k = T_k/g_k, a = K+0.001
    {
        const float ALPHA = 256.001f;
        float kf = (float)tid;
        float T  = ALPHA / (kf - ALPHA);
        float g  = sqrtf(ALPHA + T);
        sg[tid] = g;
        sh[tid] = T / g;
    }
    __syncthreads();

    const int row = blockIdx.x * WARPS_PER_BLOCK + warp;
    if (row >= nrows) return;

    const int kbase = lane * 8;

    // g/h slice for this lane's 8 classes (vectorized shared loads)
    float4 ga = *(const float4*)&sg[kbase];
    float4 gb = *(const float4*)&sg[kbase + 4];
    float4 ha = *(const float4*)&sh[kbase];
    float4 hb = *(const float4*)&sh[kbase + 4];
    const float g[8] = {ga.x, ga.y, ga.z, ga.w, gb.x, gb.y, gb.z, gb.w};
    const float h[8] = {ha.x, ha.y, ha.z, ha.w, hb.x, hb.y, hb.z, hb.w};

    // Per-row scalars
    const float L2E = 1.4426950408889634f;
    const float tv  = __ldg(t + row);
    const int   x   = __ldg(data + row);
    float sb = fminf(tv, 1.0f - 1e-6f);
    sb = fmaxf(sb, 1e-10f);
    const float sb2 = sb * L2E;                 // sb * log2(e)
    const float kb2 = 256.0f * (sb * sb) * L2E; // K * beta * log2(e)
    // Row-uniform shift instead of exact max: c = kb2 + 40.
    // Largest exponent = sb2*y - 40; overflow needs y > ~7.2 sigma (never);
    // underflow gives harmless zeros / tiny normals. Softmax-invariant.
    const float cofs = kb2 + 40.0f;

    // Load 8 noise values (coalesced float4 x2)
    const float4* nrow = noise + (size_t)row * (KCLS / 4);
    float4 n0 = __ldg(nrow + lane * 2 + 0);
    float4 n1 = __ldg(nrow + lane * 2 + 1);
    float v[8] = {n0.x, n0.y, n0.z, n0.w, n1.x, n1.y, n1.z, n1.w};

    // Pass 1: lane total of h*v (tree order - order-free, short latency)
    float hv[8];
    #pragma unroll
    for (int i = 0; i < 8; i++) hv[i] = h[i] * v[i];
    float run = ((hv[0] + hv[1]) + (hv[2] + hv[3])) + ((hv[4] + hv[5]) + (hv[6] + hv[7]));

    // Warp inclusive scan of lane totals
    float inc = run;
    #pragma unroll
    for (int d = 1; d < 32; d <<= 1) {
        float nb = __shfl_up_sync(0xFFFFFFFFu, inc, d);
        if (lane >= d) inc += nb;
    }
    const float excl = inc - run;   // exclusive prefix (saves a SHFL)

    // Pass 2: running prefix fused with logit + exp2.
    //   lg_i = sb2*(g_i*v_i + prefix_i) + (k==x ? kb2 : 0) - c
    float e[8];
    float run2 = excl;
    float s = 0.0f;
    #pragma unroll
    for (int i = 0; i < 8; i++) {
        float y  = fmaf(g[i], v[i], run2);
        float lg = fmaf(sb2, y, (kbase + i == x) ? (kb2 - cofs) : -cofs);
        run2 = fmaf(h[i], v[i], run2);
        e[i] = ex2f(lg);
        s += e[i];
    }

    // Warp sum via butterfly (only cross-lane reduction left)
    #pragma unroll
    for (int d = 16; d >= 1; d >>= 1)
        s += __shfl_xor_sync(0xFFFFFFFFu, s, d);

    const float rr = rcpf(s);
    float4* orow = out + (size_t)row * (KCLS / 4);
    orow[lane * 2 + 0] = make_float4(e[0]*rr, e[1]*rr, e[2]*rr, e[3]*rr);
    orow[lane * 2 + 1] = make_float4(e[4]*rr, e[5]*rr, e[6]*rr, e[7]*rr);
}

extern "C" void kernel_launch(void* const* d_in, const int* in_sizes, int n_in,
                              void* d_out, int out_size)
{
    const int*    data  = (const int*)d_in[0];
    const float*  t     = (const float*)d_in[1];
    const float4* noise = (const float4*)d_in[2];
    float4*       out   = (float4*)d_out;

    const int nrows = in_sizes[0];   // B*S = 16384
    const int blocks = (nrows + WARPS_PER_BLOCK - 1) / WARPS_PER_BLOCK;
    dbf_kernel<<<blocks, THREADS>>>(data, t, noise, out, nrows);
}